// round 2
// baseline (speedup 1.0000x reference)
#include <cuda_runtime.h>

// ---------------------------------------------------------------------------
// CurveChannel fused single kernel.
// out[b,0,h,w] = clamp( sum_c sum_p conv_w[c]*slopes[p,c]*relu(x[b,c,h,w]
//                       - shift[p,c]) + conv_b, 0, 1 )
//
// Each block self-loads the tiny parameter tables (L2-resident after wave 1)
// and compacts nonzero-slope breakpoints per channel (1 per channel in this
// dataset). Each thread handles 4 float4 output groups -> 12 independent
// LDG.128 front-batched for high MLP; pure streaming otherwise.
// ---------------------------------------------------------------------------

#define NPTS   16
#define IN_CH  3
#define HW4    (512 * 512 / 4)   // float4 groups per (b,c) plane = 65536
#define GPT    4                 // groups per thread
#define TPB    256               // threads per block
#define GPB    (GPT * TPB)       // groups per block = 1024
#define BLKS_PER_BATCH (HW4 / GPB)  // 64

__global__ __launch_bounds__(TPB) void curve_fused(
    const float* __restrict__ x,       // (8, 3, 512, 512)
    const float* __restrict__ shift,   // (NPTS, C)
    const float* __restrict__ slopes,  // (NPTS, C)
    const float* __restrict__ conv_w,  // (C,)
    const float* __restrict__ conv_b,  // (1,)
    float* __restrict__ out)           // (8, 1, 512, 512)
{
    __shared__ float s_raw_sl[NPTS * IN_CH];
    __shared__ float s_raw_sh[NPTS * IN_CH];
    __shared__ float s_w[IN_CH];
    __shared__ float s_bias;
    __shared__ int   s_cnt[IN_CH];
    __shared__ float s_shift[IN_CH][NPTS];
    __shared__ float s_ws[IN_CH][NPTS];

    const int tid = threadIdx.x;

    // stage raw params (48+48+3+1 floats) into shared
    if (tid < NPTS * IN_CH) {
        s_raw_sl[tid] = slopes[tid];
        s_raw_sh[tid] = shift[tid];
    }
    if (tid < IN_CH) s_w[tid] = conv_w[tid];
    if (tid == 0)    s_bias = conv_b[0];
    __syncthreads();

    // ---- issue all x loads NOW so they are in flight during compaction ----
    const int b  = blockIdx.x / BLKS_PER_BATCH;           // batch index
    const int bg = (blockIdx.x % BLKS_PER_BATCH) * GPB;   // group base in plane
    const float4* xb = reinterpret_cast<const float4*>(x) +
                       (size_t)b * (IN_CH * HW4);

    float4 xv[IN_CH][GPT];
    #pragma unroll
    for (int c = 0; c < IN_CH; ++c) {
        #pragma unroll
        for (int u = 0; u < GPT; ++u) {
            xv[c][u] = __ldg(&xb[c * HW4 + bg + u * TPB + tid]);
        }
    }

    // ---- thread 0 compacts nonzero breakpoints (overlaps with loads) ----
    if (tid == 0) {
        #pragma unroll
        for (int c = 0; c < IN_CH; ++c) {
            float w = s_w[c];
            int n = 0;
            #pragma unroll
            for (int p = 0; p < NPTS; ++p) {
                float s = s_raw_sl[p * IN_CH + c];
                if (s != 0.0f) {
                    s_shift[c][n] = s_raw_sh[p * IN_CH + c];
                    s_ws[c][n]    = s * w;
                    ++n;
                }
            }
            s_cnt[c] = n;
        }
    }
    __syncthreads();

    const float bias = s_bias;
    float4 acc[GPT];
    #pragma unroll
    for (int u = 0; u < GPT; ++u)
        acc[u] = make_float4(bias, bias, bias, bias);

    #pragma unroll
    for (int c = 0; c < IN_CH; ++c) {
        const int n = s_cnt[c];
        #pragma unroll 1
        for (int j = 0; j < n; ++j) {
            const float sh = s_shift[c][j];
            const float w  = s_ws[c][j];
            #pragma unroll
            for (int u = 0; u < GPT; ++u) {
                acc[u].x = fmaf(w, fmaxf(xv[c][u].x - sh, 0.0f), acc[u].x);
                acc[u].y = fmaf(w, fmaxf(xv[c][u].y - sh, 0.0f), acc[u].y);
                acc[u].z = fmaf(w, fmaxf(xv[c][u].z - sh, 0.0f), acc[u].z);
                acc[u].w = fmaf(w, fmaxf(xv[c][u].w - sh, 0.0f), acc[u].w);
            }
        }
    }

    float4* ob = reinterpret_cast<float4*>(out) + (size_t)b * HW4 + bg;
    #pragma unroll
    for (int u = 0; u < GPT; ++u) {
        float4 a = acc[u];
        a.x = fminf(fmaxf(a.x, 0.0f), 1.0f);
        a.y = fminf(fmaxf(a.y, 0.0f), 1.0f);
        a.z = fminf(fmaxf(a.z, 0.0f), 1.0f);
        a.w = fminf(fmaxf(a.w, 0.0f), 1.0f);
        ob[u * TPB + tid] = a;
    }
}

extern "C" void kernel_launch(void* const* d_in, const int* in_sizes, int n_in,
                              void* d_out, int out_size)
{
    const float* x      = (const float*)d_in[0];
    const float* shift  = (const float*)d_in[1];
    const float* slopes = (const float*)d_in[2];
    const float* conv_w = (const float*)d_in[3];
    const float* conv_b = (const float*)d_in[4];
    float* out = (float*)d_out;

    const int total_groups = out_size / 4;       // 524288
    const int blocks = total_groups / GPB;       // 512
    curve_fused<<<blocks, TPB>>>(x, shift, slopes, conv_w, conv_b, out);
}